// round 4
// baseline (speedup 1.0000x reference)
#include <cuda_runtime.h>

#define BB 1024
#define T_HIST 50
#define ENC_IN 96
#define ENC_H 128
#define G4 (4*ENC_H)          // 512
#define CDE_H 64
#define CHN 33
#define NZ 10000
#define MLP_H 128
#define W2_ROWS (CHN*CDE_H)   // 2112
#define N_STEPS 16

// ----------------------------------------------------------------------------
// Scratch (static device globals — no allocation)
// ----------------------------------------------------------------------------
__device__ float g_xW[BB*T_HIST*G4];      // input-to-hidden precompute (both layers, reused)
__device__ float g_seq0[BB*T_HIST*ENC_H]; // layer-0 hidden sequence
__device__ float g_h1[2][BB*ENC_H];       // layer-1 h ping-pong
__device__ float g_c[BB*ENC_H];           // LSTM cell state (reused across layers)
__device__ float g_z[BB*CDE_H];           // CDE state
__device__ float g_k[6][BB*CDE_H];        // RK45 stage derivatives
__device__ float g_a[BB*MLP_H];           // relu(zn@W1^T + b1)
__device__ float g_f[BB*W2_ROWS];         // tanh(a@W2^T + b2)

// ----------------------------------------------------------------------------
// Generic C = act(A @ B^T + bias). A:[M,K], B:[N,K], row-major, K%16==0, M%64==0.
// 64x64 tile, 256 threads, 4x4 register microtile.
// ACT: 0 none, 1 tanh, 2 relu
// ----------------------------------------------------------------------------
template<int ACT>
__global__ void __launch_bounds__(256)
gemm_tn(const float* __restrict__ A, const float* __restrict__ Bm,
        const float* __restrict__ bias, float* __restrict__ C,
        int M, int N, int K)
{
    __shared__ __align__(16) float As[16][64];
    __shared__ __align__(16) float Bs[16][64];
    const int m0 = blockIdx.x * 64;
    const int n0 = blockIdx.y * 64;
    const int tid = threadIdx.x;
    const int tr = tid >> 4;   // 0..15 -> rows tr*4..tr*4+3
    const int tc = tid & 15;   // 0..15 -> cols tc*4..tc*4+3

    float acc[4][4];
#pragma unroll
    for (int i = 0; i < 4; i++)
#pragma unroll
        for (int j = 0; j < 4; j++) acc[i][j] = 0.f;

    const int ml = tid >> 2;          // 0..63
    const int kq = (tid & 3) * 4;     // 0,4,8,12

    for (int k0 = 0; k0 < K; k0 += 16) {
        {
            float4 v = *(const float4*)(A + (size_t)(m0 + ml) * K + k0 + kq);
            As[kq+0][ml] = v.x; As[kq+1][ml] = v.y; As[kq+2][ml] = v.z; As[kq+3][ml] = v.w;
            float4 w = make_float4(0.f, 0.f, 0.f, 0.f);
            if (n0 + ml < N)
                w = *(const float4*)(Bm + (size_t)(n0 + ml) * K + k0 + kq);
            Bs[kq+0][ml] = w.x; Bs[kq+1][ml] = w.y; Bs[kq+2][ml] = w.z; Bs[kq+3][ml] = w.w;
        }
        __syncthreads();
#pragma unroll
        for (int kk = 0; kk < 16; kk++) {
            float4 a4 = *(const float4*)&As[kk][tr*4];
            float4 b4 = *(const float4*)&Bs[kk][tc*4];
            float av[4] = {a4.x, a4.y, a4.z, a4.w};
            float bv[4] = {b4.x, b4.y, b4.z, b4.w};
#pragma unroll
            for (int i = 0; i < 4; i++)
#pragma unroll
                for (int j = 0; j < 4; j++) acc[i][j] += av[i] * bv[j];
        }
        __syncthreads();
    }

#pragma unroll
    for (int j = 0; j < 4; j++) {
        int n = n0 + tc*4 + j;
        if (n >= N) continue;
        float bb = bias ? bias[n] : 0.f;
#pragma unroll
        for (int i = 0; i < 4; i++) {
            float v = acc[i][j] + bb;
            if (ACT == 1) v = tanhf(v);
            else if (ACT == 2) v = fmaxf(v, 0.f);
            C[(size_t)(m0 + tr*4 + i) * N + n] = v;
        }
    }
}

// ----------------------------------------------------------------------------
// One LSTM recurrence step, fused: g = xw[t] + h_prev@Whh^T + bih + bhh;
// gates; c,h update. Tile: 32 batch rows x 32 h-cols (all 4 gate chunks).
// grid (B/32, ENC_H/32) = (32,4) = 128 CTAs, 256 threads.
// ----------------------------------------------------------------------------
__global__ void __launch_bounds__(256)
lstm_step(const float* __restrict__ xw, int xw_sb,
          const float* __restrict__ Whh,
          const float* __restrict__ bih, const float* __restrict__ bhh,
          const float* __restrict__ h_prev, int hp_sb,
          float* __restrict__ c_buf,
          float* __restrict__ h_out, int ho_sb,
          int first)
{
    __shared__ __align__(16) float Ws[16][128];
    __shared__ __align__(16) float As[16][32];
    __shared__ float Gs[32][132];
    const int b0 = blockIdx.x * 32;
    const int h0 = blockIdx.y * 32;
    const int tid = threadIdx.x;
    const int tr = tid >> 5;   // 0..7 -> rows tr*4..+3
    const int tc = tid & 31;   // cols tc*4..+3 of 128 assembled gate-cols

    float acc[4][4];
#pragma unroll
    for (int i = 0; i < 4; i++)
#pragma unroll
        for (int j = 0; j < 4; j++) acc[i][j] = 0.f;

    if (!first) {
        for (int k0 = 0; k0 < ENC_H; k0 += 16) {
#pragma unroll
            for (int q = 0; q < 2; q++) {
                int e = tid + q * 256;           // 0..511
                int c = e >> 2;
                int kq = (e & 3) * 4;
                int jg = (c >> 5) * ENC_H + h0 + (c & 31);
                float4 v = *(const float4*)(Whh + (size_t)jg * ENC_H + k0 + kq);
                Ws[kq+0][c] = v.x; Ws[kq+1][c] = v.y; Ws[kq+2][c] = v.z; Ws[kq+3][c] = v.w;
            }
#pragma unroll
            for (int q = 0; q < 2; q++) {
                int e = tid + q * 256;           // 0..511
                int m = e >> 4, kk = e & 15;
                As[kk][m] = h_prev[(size_t)(b0 + m) * hp_sb + k0 + kk];
            }
            __syncthreads();
#pragma unroll
            for (int kk = 0; kk < 16; kk++) {
                float4 a4 = *(const float4*)&As[kk][tr*4];
                float4 w4 = *(const float4*)&Ws[kk][tc*4];
                float av[4] = {a4.x, a4.y, a4.z, a4.w};
                float wv[4] = {w4.x, w4.y, w4.z, w4.w};
#pragma unroll
                for (int i = 0; i < 4; i++)
#pragma unroll
                    for (int j = 0; j < 4; j++) acc[i][j] += av[i] * wv[j];
            }
            __syncthreads();
        }
    }

    // epilogue: add xw + biases into Gs
#pragma unroll
    for (int j = 0; j < 4; j++) {
        int c = tc*4 + j;
        int jg = (c >> 5) * ENC_H + h0 + (c & 31);
        float bb = bih[jg] + bhh[jg];
#pragma unroll
        for (int i = 0; i < 4; i++) {
            int b = b0 + tr*4 + i;
            Gs[tr*4 + i][c] = acc[i][j] + xw[(size_t)b * xw_sb + jg] + bb;
        }
    }
    __syncthreads();

    // gates: 32 rows x 32 h = 1024 outputs / 256 threads
#pragma unroll
    for (int q = 0; q < 4; q++) {
        int e = tid + q * 256;
        int r = e >> 5, hh = e & 31;
        float gi = Gs[r][hh];
        float gf = Gs[r][32 + hh];
        float gg = Gs[r][64 + hh];
        float go = Gs[r][96 + hh];
        float si = 1.f / (1.f + expf(-gi));
        float sf = 1.f / (1.f + expf(-gf));
        float so = 1.f / (1.f + expf(-go));
        float tg = tanhf(gg);
        int b = b0 + r, hg = h0 + hh;
        float cold = first ? 0.f : c_buf[(size_t)b * ENC_H + hg];
        float cn = sf * cold + si * tg;
        float hn = so * tanhf(cn);
        c_buf[(size_t)b * ENC_H + hg] = cn;
        h_out[(size_t)b * ho_sb + hg] = hn;
    }
}

// ----------------------------------------------------------------------------
// CDE stage prep: zs = z + sum a_j * k_j (a_j include dt); LayerNorm(gamma,beta);
// a = relu(zn @ W1^T + b1). grid = B/32, 256 threads.
// ----------------------------------------------------------------------------
__global__ void __launch_bounds__(256)
cde_prep(const float* __restrict__ gamma, const float* __restrict__ beta,
         const float* __restrict__ W1, const float* __restrict__ b1,
         float a0, float a1, float a2, float a3, float a4, int nk)
{
    __shared__ __align__(16) float znT[64][36];
    __shared__ __align__(16) float pool[8192];   // zs[32][65] then W1s[64][128]
    __shared__ float mu[32], rstd[32];
    const int b0 = blockIdx.x * 32;
    const int tid = threadIdx.x;
    const float av[5] = {a0, a1, a2, a3, a4};
    float* zs = pool;

#pragma unroll
    for (int q = 0; q < 8; q++) {
        int e = tid + q * 256;               // 0..2047
        int r = e >> 6, k = e & 63;
        size_t gi = (size_t)(b0 + r) * CDE_H + k;
        float v = g_z[gi];
        for (int j = 0; j < nk; j++) v += av[j] * g_k[j][gi];
        zs[r * 65 + k] = v;
    }
    __syncthreads();
    if (tid < 32) {
        float s = 0.f;
        for (int k = 0; k < 64; k++) s += zs[tid * 65 + k];
        float m = s * (1.f / 64.f);
        float q2 = 0.f;
        for (int k = 0; k < 64; k++) { float d = zs[tid * 65 + k] - m; q2 += d * d; }
        mu[tid] = m;
        rstd[tid] = rsqrtf(q2 * (1.f / 64.f) + 1e-5f);
    }
    __syncthreads();
#pragma unroll
    for (int q = 0; q < 8; q++) {
        int e = tid + q * 256;
        int k = e >> 5, r = e & 31;
        znT[k][r] = (zs[r * 65 + k] - mu[r]) * rstd[r] * gamma[k] + beta[k];
    }
    __syncthreads();

    // load W1 transposed into pool as [k][j] (overwrites zs region)
    float* W1s = pool;
#pragma unroll
    for (int q = 0; q < 32; q++) {
        int e = tid + q * 256;               // 0..8191
        int j = e >> 6, k = e & 63;
        W1s[k * 128 + j] = W1[e];
    }
    __syncthreads();

    const int tr = tid >> 5;   // rows tr*4
    const int tc = tid & 31;   // cols tc*4 of 128
    float acc[4][4];
#pragma unroll
    for (int i = 0; i < 4; i++)
#pragma unroll
        for (int j = 0; j < 4; j++) acc[i][j] = 0.f;
    for (int k = 0; k < 64; k++) {
        float zf[4];
#pragma unroll
        for (int i = 0; i < 4; i++) zf[i] = znT[k][tr*4 + i];
        float4 w4 = *(const float4*)&W1s[k * 128 + tc*4];
        float wv[4] = {w4.x, w4.y, w4.z, w4.w};
#pragma unroll
        for (int i = 0; i < 4; i++)
#pragma unroll
            for (int j = 0; j < 4; j++) acc[i][j] += zf[i] * wv[j];
    }
#pragma unroll
    for (int j = 0; j < 4; j++) {
        int col = tc*4 + j;
        float bb = b1[col];
#pragma unroll
        for (int i = 0; i < 4; i++) {
            g_a[(size_t)(b0 + tr*4 + i) * MLP_H + col] = fmaxf(acc[i][j] + bb, 0.f);
        }
    }
}

// ----------------------------------------------------------------------------
// k_s[b][h] = sum_ch f[b][h*33+ch] * dX[b][ch]; stage 6 also applies DP45 update.
// grid = B blocks, 64 threads (one per h).
// ----------------------------------------------------------------------------
__global__ void __launch_bounds__(64)
cde_contract(const float* __restrict__ coeffs, int sidx, int idx, float u,
             int do_update, float c1, float c3, float c4, float c5, float c6)
{
    __shared__ float dX[CHN];
    const int b = blockIdx.x;
    const int tid = threadIdx.x;
    if (tid < CHN) {
        size_t base = ((size_t)b * 4 + idx) * 4 * CHN;
        float A1 = coeffs[base + 1 * CHN + tid];
        float A2 = coeffs[base + 2 * CHN + tid];
        float A3 = coeffs[base + 3 * CHN + tid];
        dX[tid] = A1 + 2.f * A2 * u + 3.f * A3 * u * u;
    }
    __syncthreads();
    const float* fr = g_f + (size_t)b * W2_ROWS + tid * CHN;
    float acc = 0.f;
#pragma unroll
    for (int ch = 0; ch < CHN; ch++) acc += fr[ch] * dX[ch];
    size_t gi = (size_t)b * CDE_H + tid;
    g_k[sidx][gi] = acc;
    if (do_update) {
        g_z[gi] += c1 * g_k[0][gi] + c3 * g_k[2][gi] + c4 * g_k[3][gi]
                 + c5 * g_k[4][gi] + c6 * acc;
    }
}

// ----------------------------------------------------------------------------
// Host orchestration
// ----------------------------------------------------------------------------
extern "C" void kernel_launch(void* const* d_in, const int* in_sizes, int n_in,
                              void* d_out, int out_size)
{
    const float* hist   = (const float*)d_in[0];
    const float* coeffs = (const float*)d_in[1];
    // d_in[2] = cde_times = [0,1] (deterministic; baked in)
    const float* W_ih0 = (const float*)d_in[3];
    const float* W_hh0 = (const float*)d_in[4];
    const float* b_ih0 = (const float*)d_in[5];
    const float* b_hh0 = (const float*)d_in[6];
    const float* W_ih1 = (const float*)d_in[7];
    const float* W_hh1 = (const float*)d_in[8];
    const float* b_ih1 = (const float*)d_in[9];
    const float* b_hh1 = (const float*)d_in[10];
    const float* W_map = (const float*)d_in[11];
    const float* b_map = (const float*)d_in[12];
    const float* gamma = (const float*)d_in[13];
    const float* beta  = (const float*)d_in[14];
    const float* W1    = (const float*)d_in[15];
    const float* b1    = (const float*)d_in[16];
    const float* W2    = (const float*)d_in[17];
    const float* b2    = (const float*)d_in[18];
    const float* W_pred = (const float*)d_in[19];
    const float* b_pred = (const float*)d_in[20];
    float* out = (float*)d_out;

    float *p_xW, *p_seq0, *p_h1, *p_c, *p_z, *p_a, *p_f;
    cudaGetSymbolAddress((void**)&p_xW,   g_xW);
    cudaGetSymbolAddress((void**)&p_seq0, g_seq0);
    cudaGetSymbolAddress((void**)&p_h1,   g_h1);
    cudaGetSymbolAddress((void**)&p_c,    g_c);
    cudaGetSymbolAddress((void**)&p_z,    g_z);
    cudaGetSymbolAddress((void**)&p_a,    g_a);
    cudaGetSymbolAddress((void**)&p_f,    g_f);

    // ---------------- LSTM layer 0 ----------------
    gemm_tn<0><<<dim3(BB*T_HIST/64, G4/64), 256>>>(hist, W_ih0, nullptr, p_xW,
                                                   BB*T_HIST, G4, ENC_IN);
    for (int t = 0; t < T_HIST; t++) {
        lstm_step<<<dim3(BB/32, ENC_H/32), 256>>>(
            p_xW + (size_t)t * G4, T_HIST * G4,
            W_hh0, b_ih0, b_hh0,
            (t ? p_seq0 + (size_t)(t-1) * ENC_H : nullptr), T_HIST * ENC_H,
            p_c,
            p_seq0 + (size_t)t * ENC_H, T_HIST * ENC_H,
            (t == 0) ? 1 : 0);
    }

    // ---------------- LSTM layer 1 ----------------
    gemm_tn<0><<<dim3(BB*T_HIST/64, G4/64), 256>>>(p_seq0, W_ih1, nullptr, p_xW,
                                                   BB*T_HIST, G4, ENC_H);
    for (int t = 0; t < T_HIST; t++) {
        lstm_step<<<dim3(BB/32, ENC_H/32), 256>>>(
            p_xW + (size_t)t * G4, T_HIST * G4,
            W_hh1, b_ih1, b_hh1,
            (t ? p_h1 + (size_t)((t-1) & 1) * BB * ENC_H : nullptr), ENC_H,
            p_c,
            p_h1 + (size_t)(t & 1) * BB * ENC_H, ENC_H,
            (t == 0) ? 1 : 0);
    }
    const float* context = p_h1 + (size_t)((T_HIST - 1) & 1) * BB * ENC_H;

    // ---------------- map to z0 ----------------
    gemm_tn<1><<<dim3(BB/64, 1), 256>>>(context, W_map, b_map, p_z, BB, CDE_H, ENC_H);

    // ---------------- Neural CDE, RK45 (Dormand-Prince) ----------------
    const double dt = 1.0 / N_STEPS;
    const double ACF[6][5] = {
        {0, 0, 0, 0, 0},
        {1.0/5, 0, 0, 0, 0},
        {3.0/40, 9.0/40, 0, 0, 0},
        {44.0/45, -56.0/15, 32.0/9, 0, 0},
        {19372.0/6561, -25360.0/2187, 64448.0/6561, -212.0/729, 0},
        {9017.0/3168, -355.0/33, 46732.0/5247, 49.0/176, -5103.0/18656}
    };
    const double COFF[6] = {0.0, 1.0/5, 3.0/10, 4.0/5, 8.0/9, 1.0};
    const double BU[5] = {35.0/384, 500.0/1113, 125.0/192, -2187.0/6784, 11.0/84};

    for (int i = 0; i < N_STEPS; i++) {
        float t = (float)i * (float)dt;
        for (int s = 0; s < 6; s++) {
            cde_prep<<<BB/32, 256>>>(gamma, beta, W1, b1,
                (float)(dt*ACF[s][0]), (float)(dt*ACF[s][1]), (float)(dt*ACF[s][2]),
                (float)(dt*ACF[s][3]), (float)(dt*ACF[s][4]), s);

            gemm_tn<1><<<dim3(BB/64, W2_ROWS/64), 256>>>(p_a, W2, b2, p_f,
                                                         BB, W2_ROWS, MLP_H);

            float ts = t + (float)(dt * COFF[s]);
            int idx = (int)floorf(ts / 0.25f);
            if (idx < 0) idx = 0;
            if (idx > 3) idx = 3;
            float u = ts - (float)idx * 0.25f;
            cde_contract<<<BB, CDE_H>>>(coeffs, s, idx, u, (s == 5) ? 1 : 0,
                (float)(dt*BU[0]), (float)(dt*BU[1]), (float)(dt*BU[2]),
                (float)(dt*BU[3]), (float)(dt*BU[4]));
        }
    }

    // ---------------- final projection ----------------
    gemm_tn<0><<<dim3(BB/64, (NZ + 63)/64), 256>>>(p_z, W_pred, b_pred, out,
                                                   BB, NZ, CDE_H);
}